// round 1
// baseline (speedup 1.0000x reference)
#include <cuda_runtime.h>
#include <math.h>

// ---------------- problem constants ----------------
#define D_MODEL 512
#define NHEAD   8
#define DHEAD   64
#define NLAYER  8
#define FF      2048
#define NMEL    80
#define BATCH   8
#define SEQ     1024
#define MROWS   (BATCH*SEQ)   // 8192

// ---------------- scratch (device globals; no allocation allowed) ----------------
__device__ float g_h[MROWS * D_MODEL];   // residual stream
__device__ float g_x[MROWS * D_MODEL];   // ln output / attention ctx / final hf
__device__ float g_q[MROWS * D_MODEL];
__device__ float g_k[MROWS * D_MODEL];
__device__ float g_v[MROWS * D_MODEL];
__device__ float g_t[MROWS * FF];        // ffn intermediate
__device__ float g_pool[BATCH * D_MODEL];

// ---------------- GEMM: C[M,N] = A[M,K] @ B[K,N] + bias (+ epilogue) ----------------
enum { EPI_NONE = 0, EPI_RES = 1, EPI_GELU = 2, EPI_PE = 3 };

template<int EPI>
__global__ void __launch_bounds__(256) sgemm_k(
    const float* __restrict__ A, const float* __restrict__ Bm,
    const float* __restrict__ bias, const float* __restrict__ res,
    float* __restrict__ C, int M, int N, int K)
{
    __shared__ float As[8][128];
    __shared__ float Bs[8][128];

    const int m0 = blockIdx.y * 128;
    const int n0 = blockIdx.x * 128;
    const int tid = threadIdx.x;
    const int tx = tid & 15;          // 0..15
    const int ty = tid >> 4;          // 0..15

    // A-tile load: 128 rows x 8 k -> 4 consecutive k per thread
    const int arow = tid >> 1;            // 0..127
    const int acol = (tid & 1) * 4;       // 0 or 4
    // B-tile load: 8 k x 128 cols -> 4 consecutive n per thread
    const int brow = tid >> 5;            // 0..7
    const int bcol = (tid & 31) * 4;      // 0..124

    float acc[8][8];
    #pragma unroll
    for (int i = 0; i < 8; i++)
        #pragma unroll
        for (int j = 0; j < 8; j++) acc[i][j] = 0.0f;

    for (int k0 = 0; k0 < K; k0 += 8) {
        const int gm = m0 + arow;
        #pragma unroll
        for (int i = 0; i < 4; i++) {
            const int gk = k0 + acol + i;
            float v = 0.0f;
            if (gm < M && gk < K) v = A[(size_t)gm * K + gk];
            As[acol + i][arow] = v;
        }
        {
            const int gk = k0 + brow;
            #pragma unroll
            for (int i = 0; i < 4; i++) {
                const int gn = n0 + bcol + i;
                float v = 0.0f;
                if (gk < K && gn < N) v = Bm[(size_t)gk * N + gn];
                Bs[brow][bcol + i] = v;
            }
        }
        __syncthreads();

        #pragma unroll
        for (int kk = 0; kk < 8; kk++) {
            float ra[8], rb[8];
            #pragma unroll
            for (int i = 0; i < 8; i++) ra[i] = As[kk][ty * 8 + i];
            #pragma unroll
            for (int j = 0; j < 8; j++) rb[j] = Bs[kk][tx * 8 + j];
            #pragma unroll
            for (int i = 0; i < 8; i++)
                #pragma unroll
                for (int j = 0; j < 8; j++)
                    acc[i][j] += ra[i] * rb[j];
        }
        __syncthreads();
    }

    #pragma unroll
    for (int i = 0; i < 8; i++) {
        const int gm = m0 + ty * 8 + i;
        if (gm >= M) continue;
        #pragma unroll
        for (int j = 0; j < 8; j++) {
            const int gn = n0 + tx * 8 + j;
            if (gn >= N) continue;
            float v = acc[i][j] + bias[gn];
            if (EPI == EPI_GELU) v = 0.5f * v * (1.0f + erff(v * 0.70710678118654752f));
            if (EPI == EPI_RES)  v += res[(size_t)gm * N + gn];
            if (EPI == EPI_PE)   v += res[(size_t)(gm & (SEQ - 1)) * N + gn];
            C[(size_t)gm * N + gn] = v;
        }
    }
}

// ---------------- LayerNorm over D=512, one block per row ----------------
__global__ void __launch_bounds__(256) ln_k(
    const float* __restrict__ in, const float* __restrict__ gamma,
    const float* __restrict__ beta, float* __restrict__ out)
{
    __shared__ float warpred[8];
    __shared__ float s_mu, s_rstd;
    const int row = blockIdx.x;
    const float* x = in + (size_t)row * D_MODEL;
    const int t = threadIdx.x;

    const float v0 = x[t], v1 = x[t + 256];
    float s = v0 + v1;
    #pragma unroll
    for (int o = 16; o; o >>= 1) s += __shfl_xor_sync(0xffffffffu, s, o);
    if ((t & 31) == 0) warpred[t >> 5] = s;
    __syncthreads();
    if (t == 0) {
        float tot = 0.0f;
        #pragma unroll
        for (int i = 0; i < 8; i++) tot += warpred[i];
        s_mu = tot * (1.0f / D_MODEL);
    }
    __syncthreads();
    const float mu = s_mu;
    const float d0 = v0 - mu, d1 = v1 - mu;
    float sq = d0 * d0 + d1 * d1;
    #pragma unroll
    for (int o = 16; o; o >>= 1) sq += __shfl_xor_sync(0xffffffffu, sq, o);
    if ((t & 31) == 0) warpred[t >> 5] = sq;
    __syncthreads();
    if (t == 0) {
        float tot = 0.0f;
        #pragma unroll
        for (int i = 0; i < 8; i++) tot += warpred[i];
        s_rstd = 1.0f / sqrtf(tot * (1.0f / D_MODEL) + 1e-5f);
    }
    __syncthreads();
    const float rstd = s_rstd;
    out[(size_t)row * D_MODEL + t]       = d0 * rstd * gamma[t] + beta[t];
    out[(size_t)row * D_MODEL + t + 256] = d1 * rstd * gamma[t + 256] + beta[t + 256];
}

// ---------------- flash attention ----------------
// grid (SEQ/64, NHEAD, BATCH), 256 threads. Q/K/V in (B,S,D) layout, head h at col h*64.
// Output ctx written back in (B,S,D) layout.
#define BQ 64
#define BK 32

__global__ void __launch_bounds__(256) attn_k(
    const float* __restrict__ Q, const float* __restrict__ Kt,
    const float* __restrict__ V, float* __restrict__ O)
{
    __shared__ float Qs[BQ][DHEAD];        // 16 KB
    __shared__ float KVs[BK][DHEAD + 1];   // 8.1 KB (K, then V)
    __shared__ float Ps[BQ][BK + 1];       // 8.25 KB

    const int qt = blockIdx.x, h = blockIdx.y, b = blockIdx.z;
    const int tid = threadIdx.x;
    const int tx = tid & 15, ty = tid >> 4;

    const size_t base = (size_t)b * SEQ * D_MODEL + (size_t)h * DHEAD;

    for (int i = tid; i < BQ * DHEAD; i += 256) {
        const int r = i / DHEAD, c = i % DHEAD;
        Qs[r][c] = Q[base + (size_t)(qt * BQ + r) * D_MODEL + c];
    }

    float m_i[4], l_i[4], acc[4][4];
    #pragma unroll
    for (int i = 0; i < 4; i++) {
        m_i[i] = -INFINITY; l_i[i] = 0.0f;
        #pragma unroll
        for (int j = 0; j < 4; j++) acc[i][j] = 0.0f;
    }
    __syncthreads();

    const float scale = 0.125f;  // 1/sqrt(64)

    for (int k0 = 0; k0 < SEQ; k0 += BK) {
        // load K tile
        for (int i = tid; i < BK * DHEAD; i += 256) {
            const int r = i / DHEAD, c = i % DHEAD;
            KVs[r][c] = Kt[base + (size_t)(k0 + r) * D_MODEL + c];
        }
        __syncthreads();

        // scores: thread covers rows ty*4+i, cols tx*2+j
        float s[4][2];
        #pragma unroll
        for (int i = 0; i < 4; i++) { s[i][0] = 0.0f; s[i][1] = 0.0f; }
        #pragma unroll
        for (int kk = 0; kk < DHEAD; kk++) {
            float qv[4], kv[2];
            #pragma unroll
            for (int i = 0; i < 4; i++) qv[i] = Qs[ty * 4 + i][kk];
            kv[0] = KVs[tx * 2 + 0][kk];
            kv[1] = KVs[tx * 2 + 1][kk];
            #pragma unroll
            for (int i = 0; i < 4; i++) {
                s[i][0] += qv[i] * kv[0];
                s[i][1] += qv[i] * kv[1];
            }
        }

        float m_new[4], corr[4], tsum[4];
        #pragma unroll
        for (int i = 0; i < 4; i++) {
            s[i][0] *= scale; s[i][1] *= scale;
            float tmax = fmaxf(s[i][0], s[i][1]);
            #pragma unroll
            for (int o = 8; o; o >>= 1)
                tmax = fmaxf(tmax, __shfl_xor_sync(0xffffffffu, tmax, o));
            m_new[i] = fmaxf(m_i[i], tmax);
            corr[i]  = expf(m_i[i] - m_new[i]);
            const float p0 = expf(s[i][0] - m_new[i]);
            const float p1 = expf(s[i][1] - m_new[i]);
            Ps[ty * 4 + i][tx * 2 + 0] = p0;
            Ps[ty * 4 + i][tx * 2 + 1] = p1;
            float ts = p0 + p1;
            #pragma unroll
            for (int o = 8; o; o >>= 1)
                ts += __shfl_xor_sync(0xffffffffu, ts, o);
            tsum[i] = ts;
            l_i[i] = l_i[i] * corr[i] + tsum[i];
            m_i[i] = m_new[i];
            #pragma unroll
            for (int j = 0; j < 4; j++) acc[i][j] *= corr[i];
        }
        __syncthreads();   // Ps visible; done reading K from KVs

        // load V tile (reuse KVs)
        for (int i = tid; i < BK * DHEAD; i += 256) {
            const int r = i / DHEAD, c = i % DHEAD;
            KVs[r][c] = V[base + (size_t)(k0 + r) * D_MODEL + c];
        }
        __syncthreads();

        // acc += P * V : thread covers rows ty*4+i, cols tx*4+j
        #pragma unroll
        for (int kk = 0; kk < BK; kk++) {
            float pv[4], vv[4];
            #pragma unroll
            for (int i = 0; i < 4; i++) pv[i] = Ps[ty * 4 + i][kk];
            #pragma unroll
            for (int j = 0; j < 4; j++) vv[j] = KVs[kk][tx * 4 + j];
            #pragma unroll
            for (int i = 0; i < 4; i++)
                #pragma unroll
                for (int j = 0; j < 4; j++)
                    acc[i][j] += pv[i] * vv[j];
        }
        __syncthreads();   // done reading V before next K overwrite
    }

    #pragma unroll
    for (int i = 0; i < 4; i++) {
        const float inv = 1.0f / l_i[i];
        #pragma unroll
        for (int j = 0; j < 4; j++)
            O[base + (size_t)(qt * BQ + ty * 4 + i) * D_MODEL + tx * 4 + j] = acc[i][j] * inv;
    }
}

// ---------------- mean pool over sequence ----------------
__global__ void pool_k(const float* __restrict__ hf, float* __restrict__ pooled)
{
    const int d = blockIdx.x * blockDim.x + threadIdx.x;   // 0..511
    const int b = blockIdx.y;
    if (d >= D_MODEL) return;
    float sum = 0.0f;
    for (int s = 0; s < SEQ; s++)
        sum += hf[((size_t)b * SEQ + s) * D_MODEL + d];
    pooled[b * D_MODEL + d] = sum * (1.0f / SEQ);
}

// ---------------- tiny classification heads ----------------
__global__ void head_k(const float* __restrict__ pooled, const float* __restrict__ W,
                       const float* __restrict__ bias, float* __restrict__ out, int N)
{
    const int n = blockIdx.x * blockDim.x + threadIdx.x;
    const int b = blockIdx.y;
    if (n >= N) return;
    float sum = bias[n];
    const float* p = pooled + b * D_MODEL;
    for (int k = 0; k < D_MODEL; k++) sum += p[k] * W[(size_t)k * N + n];
    out[(size_t)b * N + n] = sum;
}

// ---------------- launch ----------------
extern "C" void kernel_launch(void* const* d_in, const int* in_sizes, int n_in,
                              void* d_out, int out_size)
{
    const float* mel    = (const float*)d_in[0];
    const float* pe     = (const float*)d_in[1];
    const float* proj_w = (const float*)d_in[2];
    const float* proj_b = (const float*)d_in[3];
    const float* Wq     = (const float*)d_in[4];
    const float* bq     = (const float*)d_in[5];
    const float* Wk     = (const float*)d_in[6];
    const float* bk     = (const float*)d_in[7];
    const float* Wv     = (const float*)d_in[8];
    const float* bv     = (const float*)d_in[9];
    const float* Wo     = (const float*)d_in[10];
    const float* bo     = (const float*)d_in[11];
    const float* ln1_g  = (const float*)d_in[12];
    const float* ln1_b  = (const float*)d_in[13];
    const float* ln2_g  = (const float*)d_in[14];
    const float* ln2_b  = (const float*)d_in[15];
    const float* Wi     = (const float*)d_in[16];
    const float* bi     = (const float*)d_in[17];
    const float* Wf     = (const float*)d_in[18];
    const float* bf     = (const float*)d_in[19];
    const float* lnf_g  = (const float*)d_in[20];
    const float* lnf_b  = (const float*)d_in[21];
    const float* lang_w = (const float*)d_in[22];
    const float* lang_b = (const float*)d_in[23];
    const float* int_w  = (const float*)d_in[24];
    const float* int_b  = (const float*)d_in[25];
    const float* emo_w  = (const float*)d_in[26];
    const float* emo_b  = (const float*)d_in[27];
    const float* sp_w   = (const float*)d_in[28];
    const float* sp_b   = (const float*)d_in[29];
    float* out = (float*)d_out;

    float *hbuf, *xbuf, *qbuf, *kbuf, *vbuf, *tbuf, *poolbuf;
    cudaGetSymbolAddress((void**)&hbuf, g_h);
    cudaGetSymbolAddress((void**)&xbuf, g_x);
    cudaGetSymbolAddress((void**)&qbuf, g_q);
    cudaGetSymbolAddress((void**)&kbuf, g_k);
    cudaGetSymbolAddress((void**)&vbuf, g_v);
    cudaGetSymbolAddress((void**)&tbuf, g_t);
    cudaGetSymbolAddress((void**)&poolbuf, g_pool);

    const dim3 gD(D_MODEL / 128, MROWS / 128);   // (4, 64) for N=512
    const dim3 gF(FF / 128, MROWS / 128);        // (16, 64) for N=2048
    const dim3 gSp((1000 + 127) / 128, MROWS / 128);

    // input projection + positional encoding
    sgemm_k<EPI_PE><<<gD, 256>>>(mel, proj_w, proj_b, pe, hbuf, MROWS, D_MODEL, NMEL);

    for (int l = 0; l < NLAYER; l++) {
        const float* wq = Wq + (size_t)l * D_MODEL * D_MODEL;
        const float* wk = Wk + (size_t)l * D_MODEL * D_MODEL;
        const float* wv = Wv + (size_t)l * D_MODEL * D_MODEL;
        const float* wo = Wo + (size_t)l * D_MODEL * D_MODEL;
        const float* wi = Wi + (size_t)l * D_MODEL * FF;
        const float* wf = Wf + (size_t)l * FF * D_MODEL;

        ln_k<<<MROWS, 256>>>(hbuf, ln1_g + l * D_MODEL, ln1_b + l * D_MODEL, xbuf);
        sgemm_k<EPI_NONE><<<gD, 256>>>(xbuf, wq, bq + l * D_MODEL, nullptr, qbuf, MROWS, D_MODEL, D_MODEL);
        sgemm_k<EPI_NONE><<<gD, 256>>>(xbuf, wk, bk + l * D_MODEL, nullptr, kbuf, MROWS, D_MODEL, D_MODEL);
        sgemm_k<EPI_NONE><<<gD, 256>>>(xbuf, wv, bv + l * D_MODEL, nullptr, vbuf, MROWS, D_MODEL, D_MODEL);
        attn_k<<<dim3(SEQ / BQ, NHEAD, BATCH), 256>>>(qbuf, kbuf, vbuf, xbuf);
        sgemm_k<EPI_RES><<<gD, 256>>>(xbuf, wo, bo + l * D_MODEL, hbuf, hbuf, MROWS, D_MODEL, D_MODEL);
        ln_k<<<MROWS, 256>>>(hbuf, ln2_g + l * D_MODEL, ln2_b + l * D_MODEL, xbuf);
        sgemm_k<EPI_GELU><<<gF, 256>>>(xbuf, wi, bi + l * FF, nullptr, tbuf, MROWS, FF, D_MODEL);
        sgemm_k<EPI_RES><<<gD, 256>>>(tbuf, wf, bf + l * D_MODEL, hbuf, hbuf, MROWS, D_MODEL, FF);
    }

    ln_k<<<MROWS, 256>>>(hbuf, lnf_g, lnf_b, xbuf);   // xbuf = hf
    pool_k<<<dim3(4, BATCH), 128>>>(xbuf, poolbuf);

    head_k<<<dim3(1, BATCH), 128>>>(poolbuf, lang_w, lang_b, out, 100);
    head_k<<<dim3(1, BATCH), 64>>>(poolbuf, int_w, int_b, out + 800, 50);
    head_k<<<dim3(1, BATCH), 32>>>(poolbuf, emo_w, emo_b, out + 1200, 8);

    // speech logits: (8192,512) @ (512,1000)
    sgemm_k<EPI_NONE><<<gSp, 256>>>(xbuf, sp_w, sp_b, nullptr, out + 1264, MROWS, 1000, D_MODEL);
}

// round 4
// speedup vs baseline: 1.3055x; 1.3055x over previous
#include <cuda_runtime.h>
#include <math.h>

// ---------------- problem constants ----------------
#define D_MODEL 512
#define NHEAD   8
#define DHEAD   64
#define NLAYER  8
#define FF      2048
#define NMEL    80
#define BATCH   8
#define SEQ     1024
#define MROWS   (BATCH*SEQ)   // 8192

// ---------------- scratch (device globals; no allocation allowed) ----------------
__device__ float g_h[MROWS * D_MODEL];   // residual stream
__device__ float g_x[MROWS * D_MODEL];   // ln output / attention ctx / final hf
__device__ float g_q[MROWS * D_MODEL];
__device__ float g_k[MROWS * D_MODEL];
__device__ float g_v[MROWS * D_MODEL];
__device__ float g_t[MROWS * FF];        // ffn intermediate
__device__ float g_pool[BATCH * D_MODEL];

// ---------------- GEMM: C[M,N] = A[M,K] @ B[K,N] + bias (+ epilogue) ----------------
// 128x128 tile, BK=16, 256 threads, 8x8 per thread, float4 everywhere,
// double-buffered smem with register prefetch of the next global tile.
// Requires: M % 128 == 0, K % 16 == 0, rows of A/B 16B-aligned (K%4==0, N%4==0).
enum { EPI_NONE = 0, EPI_RES = 1, EPI_GELU = 2, EPI_PE = 3 };

template<int EPI>
__global__ void __launch_bounds__(256, 2) sgemm_k(
    const float* __restrict__ A, const float* __restrict__ Bm,
    const float* __restrict__ bias, const float* __restrict__ res,
    float* __restrict__ C, int M, int N, int K)
{
    __shared__ float As[2][16][128];
    __shared__ float Bs[2][16][128];

    const int m0 = blockIdx.y * 128;
    const int n0 = blockIdx.x * 128;
    const int tid = threadIdx.x;
    const int tx = tid & 15;          // 0..15  -> col block tx*8
    const int ty = tid >> 4;          // 0..15  -> row block ty*8

    // A tile loader: 128 rows x 16 k; thread loads rows (ar, ar+64), k quad ak..ak+3
    const int ar = tid >> 2;          // 0..63
    const int ak = (tid & 3) * 4;     // 0,4,8,12
    // B tile loader: 16 k x 128 n; thread loads k=bk, n quads (bn, bn+64)
    const int bk = tid >> 4;          // 0..15
    const int bn = (tid & 15) * 4;    // 0..60

    const float* Arow0 = A + (size_t)(m0 + ar) * K + ak;
    const float* Arow1 = A + (size_t)(m0 + ar + 64) * K + ak;
    const float* Brow  = Bm + (size_t)bk * N;

    float acc[8][8];
    #pragma unroll
    for (int i = 0; i < 8; i++)
        #pragma unroll
        for (int j = 0; j < 8; j++) acc[i][j] = 0.0f;

    float4 va0, va1, vb0, vb1;

    // ---- load tile 0 into registers ----
    {
        va0 = *(const float4*)(Arow0);
        va1 = *(const float4*)(Arow1);
        const int gn0 = n0 + bn, gn1 = n0 + bn + 64;
        if (gn0 + 3 < N) vb0 = *(const float4*)(Brow + gn0);
        else {
            vb0.x = (gn0     < N) ? Brow[gn0]     : 0.0f;
            vb0.y = (gn0 + 1 < N) ? Brow[gn0 + 1] : 0.0f;
            vb0.z = (gn0 + 2 < N) ? Brow[gn0 + 2] : 0.0f;
            vb0.w = 0.0f;
        }
        if (gn1 + 3 < N) vb1 = *(const float4*)(Brow + gn1);
        else {
            vb1.x = (gn1     < N) ? Brow[gn1]     : 0.0f;
            vb1.y = (gn1 + 1 < N) ? Brow[gn1 + 1] : 0.0f;
            vb1.z = (gn1 + 2 < N) ? Brow[gn1 + 2] : 0.0f;
            vb1.w = 0.0f;
        }
    }
    // ---- store tile 0 to smem[0] ----
    {
        As[0][ak + 0][ar] = va0.x; As[0][ak + 1][ar] = va0.y;
        As[0][ak + 2][ar] = va0.z; As[0][ak + 3][ar] = va0.w;
        As[0][ak + 0][ar + 64] = va1.x; As[0][ak + 1][ar + 64] = va1.y;
        As[0][ak + 2][ar + 64] = va1.z; As[0][ak + 3][ar + 64] = va1.w;
        *(float4*)&Bs[0][bk][bn]      = vb0;
        *(float4*)&Bs[0][bk][bn + 64] = vb1;
    }
    __syncthreads();

    int s = 0;
    for (int k0 = 16; k0 < K; k0 += 16) {
        // ---- prefetch next tile into registers (global) ----
        va0 = *(const float4*)(Arow0 + k0);
        va1 = *(const float4*)(Arow1 + k0);
        {
            const float* Br = Brow + (size_t)k0 * N;
            const int gn0 = n0 + bn, gn1 = n0 + bn + 64;
            if (gn0 + 3 < N) vb0 = *(const float4*)(Br + gn0);
            else {
                vb0.x = (gn0     < N) ? Br[gn0]     : 0.0f;
                vb0.y = (gn0 + 1 < N) ? Br[gn0 + 1] : 0.0f;
                vb0.z = (gn0 + 2 < N) ? Br[gn0 + 2] : 0.0f;
                vb0.w = 0.0f;
            }
            if (gn1 + 3 < N) vb1 = *(const float4*)(Br + gn1);
            else {
                vb1.x = (gn1     < N) ? Br[gn1]     : 0.0f;
                vb1.y = (gn1 + 1 < N) ? Br[gn1 + 1] : 0.0f;
                vb1.z = (gn1 + 2 < N) ? Br[gn1 + 2] : 0.0f;
                vb1.w = 0.0f;
            }
        }

        // ---- compute from smem[s] ----
        #pragma unroll
        for (int kk = 0; kk < 16; kk++) {
            const float4 a0 = *(const float4*)&As[s][kk][ty * 8];
            const float4 a1 = *(const float4*)&As[s][kk][ty * 8 + 4];
            const float4 b0 = *(const float4*)&Bs[s][kk][tx * 8];
            const float4 b1 = *(const float4*)&Bs[s][kk][tx * 8 + 4];
            const float ra[8] = {a0.x, a0.y, a0.z, a0.w, a1.x, a1.y, a1.z, a1.w};
            const float rb[8] = {b0.x, b0.y, b0.z, b0.w, b1.x, b1.y, b1.z, b1.w};
            #pragma unroll
            for (int i = 0; i < 8; i++)
                #pragma unroll
                for (int j = 0; j < 8; j++)
                    acc[i][j] += ra[i] * rb[j];
        }

        // ---- write prefetched tile to the other stage ----
        const int ns = s ^ 1;
        As[ns][ak + 0][ar] = va0.x; As[ns][ak + 1][ar] = va0.y;
        As[ns][ak + 2][ar] = va0.z; As[ns][ak + 3][ar] = va0.w;
        As[ns][ak + 0][ar + 64] = va1.x; As[ns][ak + 1][ar + 64] = va1.y;
        As[ns][ak + 2][ar + 64] = va1.z; As[ns][ak + 3][ar + 64] = va1.w;
        *(float4*)&Bs[ns][bk][bn]      = vb0;
        *(float4*)&Bs[ns][bk][bn + 64] = vb1;
        __syncthreads();
        s = ns;
    }

    // ---- last tile compute ----
    #pragma unroll
    for (int kk = 0; kk < 16; kk++) {
        const float4 a0 = *(const float4*)&As[s][kk][ty * 8];
        const float4 a1 = *(const float4*)&As[s][kk][ty * 8 + 4];
        const float4 b0 = *(const float4*)&Bs[s][kk][tx * 8];
        const float4 b1 = *(const float4*)&Bs[s][kk][tx * 8 + 4];
        const float ra[8] = {a0.x, a0.y, a0.z, a0.w, a1.x, a1.y, a1.z, a1.w};
        const float rb[8] = {b0.x, b0.y, b0.z, b0.w, b1.x, b1.y, b1.z, b1.w};
        #pragma unroll
        for (int i = 0; i < 8; i++)
            #pragma unroll
            for (int j = 0; j < 8; j++)
                acc[i][j] += ra[i] * rb[j];
    }

    // ---- epilogue ----
    #pragma unroll
    for (int i = 0; i < 8; i++) {
        const int gm = m0 + ty * 8 + i;
        float* Crow = C + (size_t)gm * N;
        const float* Rrow = (EPI == EPI_RES) ? (res + (size_t)gm * N)
                          : (EPI == EPI_PE)  ? (res + (size_t)(gm & (SEQ - 1)) * N)
                          : nullptr;
        #pragma unroll
        for (int jq = 0; jq < 2; jq++) {
            const int gn = n0 + tx * 8 + jq * 4;
            float v[4];
            #pragma unroll
            for (int c = 0; c < 4; c++) {
                v[c] = acc[i][jq * 4 + c];
            }
            if (gn + 3 < N) {
                const float4 bv = *(const float4*)(bias + gn);
                v[0] += bv.x; v[1] += bv.y; v[2] += bv.z; v[3] += bv.w;
                if (EPI == EPI_GELU) {
                    #pragma unroll
                    for (int c = 0; c < 4; c++)
                        v[c] = 0.5f * v[c] * (1.0f + erff(v[c] * 0.70710678118654752f));
                }
                if (EPI == EPI_RES || EPI == EPI_PE) {
                    const float4 rv = *(const float4*)(Rrow + gn);
                    v[0] += rv.x; v[1] += rv.y; v[2] += rv.z; v[3] += rv.w;
                }
                float4 o; o.x = v[0]; o.y = v[1]; o.z = v[2]; o.w = v[3];
                *(float4*)(Crow + gn) = o;
            } else {
                #pragma unroll
                for (int c = 0; c < 4; c++) {
                    const int g = gn + c;
                    if (g < N) {
                        float vv = v[c] + bias[g];
                        if (EPI == EPI_GELU)
                            vv = 0.5f * vv * (1.0f + erff(vv * 0.70710678118654752f));
                        if (EPI == EPI_RES || EPI == EPI_PE) vv += Rrow[g];
                        Crow[g] = vv;
                    }
                }
            }
        }
    }
}

// ---------------- LayerNorm over D=512, one block per row ----------------
__global__ void __launch_bounds__(256) ln_k(
    const float* __restrict__ in, const float* __restrict__ gamma,
    const float* __restrict__ beta, float* __restrict__ out)
{
    __shared__ float warpred[8];
    __shared__ float s_mu, s_rstd;
    const int row = blockIdx.x;
    const float* x = in + (size_t)row * D_MODEL;
    const int t = threadIdx.x;

    const float v0 = x[t], v1 = x[t + 256];
    float s = v0 + v1;
    #pragma unroll
    for (int o = 16; o; o >>= 1) s += __shfl_xor_sync(0xffffffffu, s, o);
    if ((t & 31) == 0) warpred[t >> 5] = s;
    __syncthreads();
    if (t == 0) {
        float tot = 0.0f;
        #pragma unroll
        for (int i = 0; i < 8; i++) tot += warpred[i];
        s_mu = tot * (1.0f / D_MODEL);
    }
    __syncthreads();
    const float mu = s_mu;
    const float d0 = v0 - mu, d1 = v1 - mu;
    float sq = d0 * d0 + d1 * d1;
    #pragma unroll
    for (int o = 16; o; o >>= 1) sq += __shfl_xor_sync(0xffffffffu, sq, o);
    if ((t & 31) == 0) warpred[t >> 5] = sq;
    __syncthreads();
    if (t == 0) {
        float tot = 0.0f;
        #pragma unroll
        for (int i = 0; i < 8; i++) tot += warpred[i];
        s_rstd = 1.0f / sqrtf(tot * (1.0f / D_MODEL) + 1e-5f);
    }
    __syncthreads();
    const float rstd = s_rstd;
    out[(size_t)row * D_MODEL + t]       = d0 * rstd * gamma[t] + beta[t];
    out[(size_t)row * D_MODEL + t + 256] = d1 * rstd * gamma[t + 256] + beta[t + 256];
}

// ---------------- flash attention ----------------
#define BQ 64
#define BK 32

__global__ void __launch_bounds__(256) attn_k(
    const float* __restrict__ Q, const float* __restrict__ Kt,
    const float* __restrict__ V, float* __restrict__ O)
{
    __shared__ float Qs[BQ][DHEAD];        // 16 KB
    __shared__ float KVs[BK][DHEAD + 4];   // K, then V (pad 4 floats to dodge conflicts)
    __shared__ float Ps[BQ][BK + 1];       // 8.25 KB

    const int qt = blockIdx.x, h = blockIdx.y, b = blockIdx.z;
    const int tid = threadIdx.x;
    const int tx = tid & 15, ty = tid >> 4;

    const size_t base = (size_t)b * SEQ * D_MODEL + (size_t)h * DHEAD;

    // Q tile fill: 64 rows x 16 float4 = 1024 float4; 256 threads x 4
    {
        const int r = tid >> 2;            // 0..63
        const int c4 = (tid & 3) * 4;      // 0,4,8,12 (float4 index)
        const float4* src = (const float4*)(Q + base + (size_t)(qt * BQ + r) * D_MODEL) + c4;
        float4* dst = (float4*)&Qs[r][c4 * 4];
        #pragma unroll
        for (int i = 0; i < 4; i++) dst[i] = src[i];
    }

    float m_i[4], l_i[4], acc[4][4];
    #pragma unroll
    for (int i = 0; i < 4; i++) {
        m_i[i] = -INFINITY; l_i[i] = 0.0f;
        #pragma unroll
        for (int j = 0; j < 4; j++) acc[i][j] = 0.0f;
    }
    __syncthreads();

    const float scale = 0.125f;  // 1/sqrt(64)
    const int kvr = tid >> 3;            // 0..31
    const int kvc = (tid & 7) * 2;       // float4 idx 0,2,..,14

    for (int k0 = 0; k0 < SEQ; k0 += BK) {
        // K tile fill: 32 rows x 16 float4 = 512 float4; 256 threads x 2
        {
            const float4* src = (const float4*)(Kt + base + (size_t)(k0 + kvr) * D_MODEL) + kvc;
            float4* dst = (float4*)&KVs[kvr][kvc * 4];
            dst[0] = src[0]; dst[1] = src[1];
        }
        __syncthreads();

        float s[4][2];
        #pragma unroll
        for (int i = 0; i < 4; i++) { s[i][0] = 0.0f; s[i][1] = 0.0f; }
        #pragma unroll
        for (int kk = 0; kk < DHEAD; kk++) {
            float qv[4], kv[2];
            #pragma unroll
            for (int i = 0; i < 4; i++) qv[i] = Qs[ty * 4 + i][kk];
            kv[0] = KVs[tx * 2 + 0][kk];
            kv[1] = KVs[tx * 2 + 1][kk];
            #pragma unroll
            for (int i = 0; i < 4; i++) {
                s[i][0] += qv[i] * kv[0];
                s[i][1] += qv[i] * kv[1];
            }
        }

        float m_new[4], corr[4], tsum[4];
        #pragma unroll
        for (int i = 0; i < 4; i++) {
            s[i][0] *= scale; s[i][1] *= scale;
            float tmax = fmaxf(s[i][0], s[i][1]);
            #pragma unroll
            for (int o = 8; o; o >>= 1)
                tmax = fmaxf(tmax, __shfl_xor_sync(0xffffffffu, tmax, o));
            m_new[i] = fmaxf(m_i[i], tmax);
            corr[i]  = expf(m_i[i] - m_new[i]);
            const float p0 = expf(s[i][0] - m_new[i]);
            const float p1 = expf(s[i][1] - m_new[i]);
            Ps[ty * 4 + i][tx * 2 + 0] = p0;
            Ps[ty * 4 + i][tx * 2 + 1] = p1;
            float ts = p0 + p1;
            #pragma unroll
            for (int o = 8; o; o >>= 1)
                ts += __shfl_xor_sync(0xffffffffu, ts, o);
            tsum[i] = ts;
            l_i[i] = l_i[i] * corr[i] + tsum[i];
            m_i[i] = m_new[i];
            #pragma unroll
            for (int j = 0; j < 4; j++) acc[i][j] *= corr[i];
        }
        __syncthreads();   // Ps visible; done reading K

        // V tile fill (reuse KVs)
        {
            const float4* src = (const float4*)(V + base + (size_t)(k0 + kvr) * D_MODEL) + kvc;
            float4* dst = (float4*)&KVs[kvr][kvc * 4];
            dst[0] = src[0]; dst[1] = src[1];
        }
        __syncthreads();

        #pragma unroll
        for (int kk = 0; kk < BK; kk++) {
            float pv[4], vv[4];
            #pragma unroll
            for (int i = 0; i < 4; i++) pv[i] = Ps[ty * 4 + i][kk];
            #pragma unroll
            for (int j = 0; j < 4; j++) vv[j] = KVs[kk][tx * 4 + j];
            #pragma unroll
            for (int i = 0; i < 4; i++)
                #pragma unroll
                for (int j = 0; j < 4; j++)
                    acc[i][j] += pv[i] * vv[j];
        }
        __syncthreads();
    }

    #pragma unroll
    for (int i = 0; i < 4; i++) {
        const float inv = 1.0f / l_i[i];
        float4 o;
        o.x = acc[i][0] * inv; o.y = acc[i][1] * inv;
        o.z = acc[i][2] * inv; o.w = acc[i][3] * inv;
        *(float4*)(O + base + (size_t)(qt * BQ + ty * 4 + i) * D_MODEL + tx * 4) = o;
    }
}

// ---------------- mean pool over sequence ----------------
__global__ void pool_k(const float* __restrict__ hf, float* __restrict__ pooled)
{
    const int d = blockIdx.x * blockDim.x + threadIdx.x;   // 0..511
    const int b = blockIdx.y;
    if (d >= D_MODEL) return;
    float sum = 0.0f;
    for (int s = 0; s < SEQ; s++)
        sum += hf[((size_t)b * SEQ + s) * D_MODEL + d];
    pooled[b * D_MODEL + d] = sum * (1.0f / SEQ);
}

// ---------------- tiny classification heads ----------------
__global__ void head_k(const float* __restrict__ pooled, const float* __restrict__ W,
                       const float* __restrict__ bias, float* __restrict__ out, int N)
{
    const int n = blockIdx.x * blockDim.x + threadIdx.x;
    const int b = blockIdx.y;
    if (n >= N) return;
    float sum = bias[n];
    const float* p = pooled + b * D_MODEL;
    for (int k = 0; k < D_MODEL; k++) sum += p[k] * W[(size_t)k * N + n];
    out[(size_t)b * N + n] = sum;
}

// ---------------- launch ----------------
extern "C" void kernel_launch(void* const* d_in, const int* in_sizes, int n_in,
                              void* d_out, int out_size)
{
    const float* mel    = (const float*)d_in[0];
    const float* pe     = (const float*)d_in[1];
    const float* proj_w = (const float*)d_in[2];
    const float* proj_b = (const float*)d_in[3];
    const float* Wq     = (const float*)d_in[4];
    const float* bq     = (const float*)d_in[5];
    const float* Wk     = (const float*)d_in[6];
    const float* bk     = (const float*)d_in[7];
    const float* Wv     = (const float*)d_in[8];
    const float* bv     = (const float*)d_in[9];
    const float* Wo     = (const float*)d_in[10];
    const float* bo     = (const float*)d_in[11];
    const float* ln1_g  = (const float*)d_in[12];
    const float* ln1_b  = (const float*)d_in[13];
    const float* ln2_g  = (const float*)d_in[14];
    const float* ln2_b  = (const float*)d_in[15];
    const float* Wi     = (const float*)d_in[16];
    const float* bi     = (const float*)d_in[17];
    const float* Wf     = (const float*)d_in[18];
    const float* bf     = (const float*)d_in[19];
    const float* lnf_g  = (const float*)d_in[20];
    const float* lnf_b  = (const float*)d_in[21];
    const float* lang_w = (const float*)d_in[22];
    const float* lang_b = (const float*)d_in[23];
    const float* int_w  = (const float*)d_in[24];
    const float* int_b  = (const float*)d_in[25];
    const float* emo_w  = (const float*)d_in[26];
    const float* emo_b  = (const float*)d_in[27];
    const float* sp_w   = (const float*)d_in[28];
    const float* sp_b   = (const float*)d_in[29];
    float* out = (float*)d_out;

    float *hbuf, *xbuf, *qbuf, *kbuf, *vbuf, *tbuf, *poolbuf;
    cudaGetSymbolAddress((void**)&hbuf, g_h);
    cudaGetSymbolAddress((void**)&xbuf, g_x);
    cudaGetSymbolAddress((void**)&qbuf, g_q);
    cudaGetSymbolAddress((void**)&kbuf, g_k);
    cudaGetSymbolAddress((void**)&vbuf, g_v);
    cudaGetSymbolAddress((void**)&tbuf, g_t);
    cudaGetSymbolAddress((void**)&poolbuf, g_pool);

    const dim3 gD(D_MODEL / 128, MROWS / 128);   // (4, 64)
    const dim3 gF(FF / 128, MROWS / 128);        // (16, 64)
    const dim3 gSp((1000 + 127) / 128, MROWS / 128);

    // input projection + positional encoding (K=80, multiple of 16)
    sgemm_k<EPI_PE><<<gD, 256>>>(mel, proj_w, proj_b, pe, hbuf, MROWS, D_MODEL, NMEL);

    for (int l = 0; l < NLAYER; l++) {
        const float* wq = Wq + (size_t)l * D_MODEL * D_MODEL;
        const float* wk = Wk + (size_t)l * D_MODEL * D_MODEL;
        const float* wv = Wv + (size_t)l * D_MODEL * D_MODEL;
        const float* wo = Wo + (size_t)l * D_MODEL * D_MODEL;
        const float* wi = Wi + (size_t)l * D_MODEL * FF;
        const float* wf = Wf + (size_t)l * FF * D_MODEL;

        ln_k<<<MROWS, 256>>>(hbuf, ln1_g + l * D_MODEL, ln1_b + l * D_MODEL, xbuf);
        sgemm_k<EPI_NONE><<<gD, 256>>>(xbuf, wq, bq + l * D_MODEL, nullptr, qbuf, MROWS, D_MODEL, D_MODEL);
        sgemm_k<EPI_NONE><<<gD, 256>>>(xbuf, wk, bk + l * D_MODEL, nullptr, kbuf, MROWS, D_MODEL, D_MODEL);
        sgemm_k<EPI_NONE><<<gD, 256>>>(xbuf, wv, bv + l * D_MODEL, nullptr, vbuf, MROWS, D_MODEL, D_MODEL);
        attn_k<<<dim3(SEQ / BQ, NHEAD, BATCH), 256>>>(qbuf, kbuf, vbuf, xbuf);
        sgemm_k<EPI_RES><<<gD, 256>>>(xbuf, wo, bo + l * D_MODEL, hbuf, hbuf, MROWS, D_MODEL, D_MODEL);
        ln_k<<<MROWS, 256>>>(hbuf, ln2_g + l * D_MODEL, ln2_b + l * D_MODEL, xbuf);
        sgemm_k<EPI_GELU><<<gF, 256>>>(xbuf, wi, bi + l * FF, nullptr, tbuf, MROWS, FF, D_MODEL);
        sgemm_k<EPI_RES><<<gD, 256>>>(tbuf, wf, bf + l * D_MODEL, hbuf, hbuf, MROWS, D_MODEL, FF);
    }

    ln_k<<<MROWS, 256>>>(hbuf, lnf_g, lnf_b, xbuf);   // xbuf = hf
    pool_k<<<dim3(4, BATCH), 128>>>(xbuf, poolbuf);

    head_k<<<dim3(1, BATCH), 128>>>(poolbuf, lang_w, lang_b, out, 100);
    head_k<<<dim3(1, BATCH), 64>>>(poolbuf, int_w, int_b, out + 800, 50);
    head_k<<<dim3(1, BATCH), 32>>>(poolbuf, emo_w, emo_b, out + 1200, 8);

    // speech logits: (8192,512) @ (512,1000)
    sgemm_k<EPI_NONE><<<gSp, 256>>>(xbuf, sp_w, sp_b, nullptr, out + 1264, MROWS, 1000, D_MODEL);
}